// round 12
// baseline (speedup 1.0000x reference)
#include <cuda_runtime.h>

// OBMC two-pass, channels-last + 5-group fusion.
// R12: conflict-free smem (quad-preserving XOR swizzle), vectorized g2/g4
//      stores (interior quads + 4 scalars), conflict-free transpose.

#define BB 4
#define CC 64
#define HH 256
#define WW 256
#define HW (HH * WW)
#define PXT 16

__device__ float g_xT[(size_t)BB * HW * CC];   // 67 MB scratch

// swizzle: XOR word-column by 4 when px>=8 (keeps float4 alignment)
__device__ __forceinline__ int xorv(int px) { return ((px >> 3) & 1) << 2; }

// ---------------- Pass 1: transpose x[B,C,H,W] -> xT[B,HW,C] ----------------
// t[px][ch] with stride 33: STS (load phase) and LDS (store phase) both
// conflict-free; LDG.128 in, STG.128 out.
__global__ __launch_bounds__(256)
void obmc_transpose(const float* __restrict__ x) {
    __shared__ float t[32][33];
    const int b   = blockIdx.z;
    const int cb  = blockIdx.y * 32;
    const int pb  = blockIdx.x * 32;
    const int tid = threadIdx.x;

    {   // load: ch = tid>>3 (0..31), px quad = tid&7
        const int ch  = tid >> 3;
        const int px4 = tid & 7;
        const float4 v = __ldcs((const float4*)(x + ((size_t)b * CC + cb + ch) * HW + pb) + px4);
        t[px4 * 4 + 0][ch] = v.x;
        t[px4 * 4 + 1][ch] = v.y;
        t[px4 * 4 + 2][ch] = v.z;
        t[px4 * 4 + 3][ch] = v.w;
    }
    __syncthreads();
    {   // store: px = tid>>3 (0..31), ch quad = tid&7
        const int px = tid >> 3;
        const int q  = tid & 7;
        float4 v;
        v.x = t[px][q * 4 + 0];
        v.y = t[px][q * 4 + 1];
        v.z = t[px][q * 4 + 2];
        v.w = t[px][q * 4 + 3];
        *(float4*)(g_xT + ((size_t)b * HW + pb + px) * CC + cb + q * 4) = v;
    }
}

// ---------------- Pass 2: fused gather + vectorized store ----------------
__global__ __launch_bounds__(256, 4)
void obmc_gather(const float* __restrict__ flow, float* __restrict__ out) {
    __shared__ __align__(16) float st[5 * PXT * 68];   // [g][px][68], swizzled cols

    const int tid = threadIdx.x;
    const int l   = tid & 31;
    const int w   = tid >> 5;
    const int pxl = (w << 1) | (l >> 4);      // flow pixel 0..15 in block
    const int ch4 = l & 15;                   // 4-channel slice
    const int X0  = blockIdx.x * PXT;
    const int Y   = blockIdx.y;
    const int b   = blockIdx.z;
    const int xp  = X0 + pxl;
    const int pix = Y * WW + xp;

    const float* fb  = flow + (size_t)b * 2 * HW;
    const float* xTb = g_xT + (size_t)b * HW * CC;

    const float fx = __ldg(fb + pix);
    const float fy = __ldg(fb + HW + pix);

    const float gx = (float)xp + fx;
    const float gy = (float)Y  + fy;
    const float x0f = floorf(gx), y0f = floorf(gy);
    const float wx = gx - x0f,    wy = gy - y0f;
    const int x0 = (int)x0f, y0 = (int)y0f;

    // factorized masked weight tables; rows r=y0-1+i, cols c=x0-1+j
    int rb_[4], cb_[4];
    float Tw[4], Bw[4], Lw[4], Rw[4];
    #pragma unroll
    for (int i = 0; i < 4; ++i) {
        const int r = y0 - 1 + i;
        const float vr = ((unsigned)r < HH) ? 1.f : 0.f;
        rb_[i] = min(max(r, 0), HH - 1) * WW;
        Tw[i] = (1.f - wy) * vr;
        Bw[i] = wy * vr;
        const int c = x0 - 1 + i;
        const float vc = ((unsigned)c < WW) ? 1.f : 0.f;
        cb_[i] = min(max(c, 0), WW - 1);
        Lw[i] = (1.f - wx) * vc;
        Rw[i] = wx * vc;
    }

    #define LOADT(nm, i, j) \
        const float4 nm = __ldg((const float4*)(xTb + (size_t)(rb_[i] + cb_[j]) * CC) + ch4);
    #define BLEND4(dst, cA, tA, cB, tB, cC, tC, cD, tD) \
        float4 dst; \
        dst.x = fmaf(cD, tD.x, fmaf(cC, tC.x, fmaf(cB, tB.x, cA * tA.x))); \
        dst.y = fmaf(cD, tD.y, fmaf(cC, tC.y, fmaf(cB, tB.y, cA * tA.y))); \
        dst.z = fmaf(cD, tD.z, fmaf(cC, tC.z, fmaf(cB, tB.z, cA * tA.z))); \
        dst.w = fmaf(cD, tD.w, fmaf(cC, tC.w, fmaf(cB, tB.w, cA * tA.w)));

    // swizzled staging base for this thread's quad
    const int cpb = (ch4 * 4) ^ xorv(pxl);
    #define STAGE(g, v) *(float4*)&st[((g) * PXT + pxl) * 68 + cpb] = v;

    // ---- wave A: rows 1,2 (8 taps) -> v0, v2, v4 ----
    LOADT(t10, 1, 0) LOADT(t11, 1, 1) LOADT(t12, 1, 2) LOADT(t13, 1, 3)
    LOADT(t20, 2, 0) LOADT(t21, 2, 1) LOADT(t22, 2, 2) LOADT(t23, 2, 3)

    BLEND4(v0, Tw[1]*Lw[1], t11, Tw[1]*Rw[2], t12, Bw[2]*Lw[1], t21, Bw[2]*Rw[2], t22)
    STAGE(0, v0)
    BLEND4(v2, Tw[1]*Lw[0], t10, Tw[1]*Rw[1], t11, Bw[2]*Lw[0], t20, Bw[2]*Rw[1], t21)
    STAGE(2, v2)
    BLEND4(v4, Tw[1]*Lw[2], t12, Tw[1]*Rw[3], t13, Bw[2]*Lw[2], t22, Bw[2]*Rw[3], t23)
    STAGE(4, v4)

    // ---- wave B: rows 0,3 (4 taps) -> v1, v3 ----
    LOADT(t01, 0, 1) LOADT(t02, 0, 2) LOADT(t31, 3, 1) LOADT(t32, 3, 2)

    BLEND4(v1, Tw[0]*Lw[1], t01, Tw[0]*Rw[2], t02, Bw[1]*Lw[1], t11, Bw[1]*Rw[2], t12)
    STAGE(1, v1)
    BLEND4(v3, Tw[2]*Lw[1], t21, Tw[2]*Rw[2], t22, Bw[3]*Lw[1], t31, Bw[3]*Rw[2], t32)
    STAGE(3, v3)

    #undef LOADT
    #undef BLEND4
    #undef STAGE

    // rare border identity copies (exact): center value = x at (Y,xp)
    if ((Y == 0) | (Y == HH - 1) | (xp == 0) | (xp == WW - 1)) {
        const float4 cv = __ldg((const float4*)(xTb + (size_t)pix * CC) + ch4);
        const float cvv[4] = {cv.x, cv.y, cv.z, cv.w};
        #pragma unroll
        for (int k = 0; k < 4; ++k) {
            const int c = ch4 * 4 + k;
            const size_t base = ((size_t)(b * 5) * CC + c) * HW + pix;
            if (Y == HH - 1)  __stcs(out + base + (size_t)1 * CC * HW, cvv[k]);
            if (Y == 0)       __stcs(out + base + (size_t)3 * CC * HW, cvv[k]);
            if (xp == WW - 1) __stcs(out + base + (size_t)2 * CC * HW, cvv[k]);
            if (xp == 0)      __stcs(out + base + (size_t)4 * CC * HW, cvv[k]);
        }
    }
    __syncthreads();

    float* ob = out + (size_t)(b * 5) * CC * HW + (size_t)Y * WW + X0;

    // ---- vec stores g0,g1,g3 (aligned 16-px segments) ----
    {
        const int c   = tid >> 2;                 // channel 0..63
        const int px4 = tid & 3;                  // px quad 0..3
        const int cph = c ^ ((px4 >> 1) << 2);    // xorv(px4*4 + 0..3)
        #pragma unroll
        for (int vi = 0; vi < 3; ++vi) {
            const int sl = (vi == 2) ? 3 : vi;
            const float* sb = st + (sl * PXT + px4 * 4) * 68 + cph;
            float4 q;
            q.x = sb[0];
            q.y = sb[68];
            q.z = sb[136];
            q.w = sb[204];
            float* p = ob + (size_t)(sl * 64 + c) * HW + px4 * 4;
            bool ok = true;
            if (sl == 1)      { p -= WW; ok = (Y >= 1); }
            else if (sl == 3) { p += WW; ok = (Y <= HH - 2); }
            if (ok) __stcs((float4*)p, q);
        }
    }

    // ---- vec stores g2,g4: 3 interior quads each (384 tasks) ----
    #pragma unroll
    for (int it = 0; it < 2; ++it) {
        const int idx = tid + it * 256;
        if (idx < 384) {
            const int isg4 = (idx >= 192);
            const int r    = idx - (isg4 ? 192 : 0);
            const int c    = r / 3;
            const int q    = r - c * 3;
            const int slot = isg4 ? 4 : 2;
            const int px0  = isg4 ? (4 * q + 3) : (4 * q + 1);   // first smem px
            float4 v;
            {
                const float* sr = st + (slot * PXT) * 68;
                v.x = sr[(px0 + 0) * 68 + (c ^ xorv(px0 + 0))];
                v.y = sr[(px0 + 1) * 68 + (c ^ xorv(px0 + 1))];
                v.z = sr[(px0 + 2) * 68 + (c ^ xorv(px0 + 2))];
                v.w = sr[(px0 + 3) * 68 + (c ^ xorv(px0 + 3))];
            }
            const int colo = isg4 ? (4 * (q + 1)) : (4 * q);     // offset from X0
            __stcs((float4*)(ob + (size_t)(slot * 64 + c) * HW + colo), v);
        }
    }

    // ---- scalar leftovers: 4 cols per (g2,g4) row (512 tasks) ----
    #pragma unroll
    for (int it = 0; it < 2; ++it) {
        const int idx  = tid + it * 256;         // 0..511
        const int isg4 = (idx >= 256);
        const int r    = idx & 255;
        const int c    = r >> 2;
        const int s    = r & 3;
        const int slot = isg4 ? 4 : 2;
        // g2 leftover px {0,13,14,15} -> cols {X0-1, X0+12..14}
        // g4 leftover px {0,1,2,15}   -> cols {X0+1..3, X0+16}
        const int px  = isg4 ? ((s == 3) ? 15 : s) : ((s == 0) ? 0 : (12 + s));
        const int col = isg4 ? (px + 1) : (px - 1);               // offset from X0
        const int gcol = X0 + col;
        if ((unsigned)gcol < WW) {
            const float v = st[(slot * PXT + px) * 68 + (c ^ xorv(px))];
            __stcs(ob + (size_t)(slot * 64 + c) * HW + col, v);
        }
    }
}

extern "C" void kernel_launch(void* const* d_in, const int* in_sizes, int n_in,
                              void* d_out, int out_size) {
    const float* x    = (const float*)d_in[0];
    const float* flow = (const float*)d_in[1];
    float* out        = (float*)d_out;

    dim3 tgrid(HW / 32, CC / 32, BB);
    obmc_transpose<<<tgrid, 256>>>(x);

    dim3 ggrid(WW / PXT, HH, BB);   // 16 x 256 x 4
    obmc_gather<<<ggrid, 256>>>(flow, out);
}

// round 14
// speedup vs baseline: 1.1055x; 1.1055x over previous
#include <cuda_runtime.h>

// OBMC two-pass, channels-last + 5-group fusion.
// R14 = R11 gather (best measured: 111us) + MLP-4 conflict-free transpose:
//       64x64 tile as four 32x32 subtiles (t[k][32][33], scalar STS/LDS both
//       bank-bijective), 4 independent LDG.128 per thread before the sync.

#define BB 4
#define CC 64
#define HH 256
#define WW 256
#define HW (HH * WW)
#define PXT 16

__device__ float g_xT[(size_t)BB * HW * CC];   // 67 MB scratch

// ---------------- Pass 1: transpose x[B,C,H,W] -> xT[B,HW,C] ----------------
__global__ __launch_bounds__(256)
void obmc_transpose(const float* __restrict__ x) {
    __shared__ float t[4][32][33];
    const int b   = blockIdx.z;
    const int pb  = blockIdx.x * 64;   // pixel-tile base within HW
    const int tid = threadIdx.x;

    {   // load: per subtile k = {chHalf, pxHalf}; ch = tid>>3, px4 = tid&7
        const int ch  = tid >> 3;      // 0..31
        const int px4 = tid & 7;       // 0..7
        float4 v[4];
        #pragma unroll
        for (int k = 0; k < 4; ++k) {
            const int chg = (k >> 1) * 32 + ch;
            const int pxg = pb + (k & 1) * 32;
            v[k] = __ldcs((const float4*)(x + ((size_t)b * CC + chg) * HW + pxg) + px4);
        }
        #pragma unroll
        for (int k = 0; k < 4; ++k) {
            t[k][px4 * 4 + 0][ch] = v[k].x;
            t[k][px4 * 4 + 1][ch] = v[k].y;
            t[k][px4 * 4 + 2][ch] = v[k].z;
            t[k][px4 * 4 + 3][ch] = v[k].w;
        }
    }
    __syncthreads();
    {   // store: px = tid>>3, chquad q = tid&7
        const int px = tid >> 3;       // 0..31
        const int q  = tid & 7;        // 0..7
        #pragma unroll
        for (int k = 0; k < 4; ++k) {
            float4 v;
            v.x = t[k][px][q * 4 + 0];
            v.y = t[k][px][q * 4 + 1];
            v.z = t[k][px][q * 4 + 2];
            v.w = t[k][px][q * 4 + 3];
            const int pxg = pb + (k & 1) * 32 + px;
            const int chg = (k >> 1) * 32 + q * 4;
            *(float4*)(g_xT + ((size_t)b * HW + pxg) * CC + chg) = v;
        }
    }
}

// ---------------- Pass 2: fused gather + vectorized store (R11) ----------------
__global__ __launch_bounds__(256, 4)
void obmc_gather(const float* __restrict__ flow, float* __restrict__ out) {
    __shared__ __align__(16) float st[5 * PXT * 68];   // [g][px][68]

    const int tid = threadIdx.x;
    const int l   = tid & 31;
    const int w   = tid >> 5;
    const int pxl = (w << 1) | (l >> 4);      // flow pixel 0..15 in block
    const int ch4 = l & 15;                   // 4-channel slice
    const int X0  = blockIdx.x * PXT;
    const int Y   = blockIdx.y;
    const int b   = blockIdx.z;
    const int xp  = X0 + pxl;
    const int pix = Y * WW + xp;

    const float* fb  = flow + (size_t)b * 2 * HW;
    const float* xTb = g_xT + (size_t)b * HW * CC;

    const float fx = __ldg(fb + pix);
    const float fy = __ldg(fb + HW + pix);

    const float gx = (float)xp + fx;
    const float gy = (float)Y  + fy;
    const float x0f = floorf(gx), y0f = floorf(gy);
    const float wx = gx - x0f,    wy = gy - y0f;
    const int x0 = (int)x0f, y0 = (int)y0f;

    // factorized masked weight tables; rows r=y0-1+i, cols c=x0-1+j
    int rb_[4], cb_[4];
    float Tw[4], Bw[4], Lw[4], Rw[4];
    #pragma unroll
    for (int i = 0; i < 4; ++i) {
        const int r = y0 - 1 + i;
        const float vr = ((unsigned)r < HH) ? 1.f : 0.f;
        rb_[i] = min(max(r, 0), HH - 1) * WW;
        Tw[i] = (1.f - wy) * vr;
        Bw[i] = wy * vr;
        const int c = x0 - 1 + i;
        const float vc = ((unsigned)c < WW) ? 1.f : 0.f;
        cb_[i] = min(max(c, 0), WW - 1);
        Lw[i] = (1.f - wx) * vc;
        Rw[i] = wx * vc;
    }

    #define LOADT(nm, i, j) \
        const float4 nm = __ldg((const float4*)(xTb + (size_t)(rb_[i] + cb_[j]) * CC) + ch4);
    #define BLEND4(dst, cA, tA, cB, tB, cC, tC, cD, tD) \
        float4 dst; \
        dst.x = fmaf(cD, tD.x, fmaf(cC, tC.x, fmaf(cB, tB.x, cA * tA.x))); \
        dst.y = fmaf(cD, tD.y, fmaf(cC, tC.y, fmaf(cB, tB.y, cA * tA.y))); \
        dst.z = fmaf(cD, tD.z, fmaf(cC, tC.z, fmaf(cB, tB.z, cA * tA.z))); \
        dst.w = fmaf(cD, tD.w, fmaf(cC, tC.w, fmaf(cB, tB.w, cA * tA.w)));

    float4* s4 = (float4*)st;                 // 17 float4 per px-row

    // ---- wave A: rows 1,2 (8 taps) -> v0, v2, v4 ----
    LOADT(t10, 1, 0) LOADT(t11, 1, 1) LOADT(t12, 1, 2) LOADT(t13, 1, 3)
    LOADT(t20, 2, 0) LOADT(t21, 2, 1) LOADT(t22, 2, 2) LOADT(t23, 2, 3)

    BLEND4(v0, Tw[1]*Lw[1], t11, Tw[1]*Rw[2], t12, Bw[2]*Lw[1], t21, Bw[2]*Rw[2], t22)
    s4[(0 * PXT + pxl) * 17 + ch4] = v0;
    BLEND4(v2, Tw[1]*Lw[0], t10, Tw[1]*Rw[1], t11, Bw[2]*Lw[0], t20, Bw[2]*Rw[1], t21)
    s4[(2 * PXT + pxl) * 17 + ch4] = v2;
    BLEND4(v4, Tw[1]*Lw[2], t12, Tw[1]*Rw[3], t13, Bw[2]*Lw[2], t22, Bw[2]*Rw[3], t23)
    s4[(4 * PXT + pxl) * 17 + ch4] = v4;

    // ---- wave B: rows 0,3 (4 taps) -> v1, v3 ----
    LOADT(t01, 0, 1) LOADT(t02, 0, 2) LOADT(t31, 3, 1) LOADT(t32, 3, 2)

    BLEND4(v1, Tw[0]*Lw[1], t01, Tw[0]*Rw[2], t02, Bw[1]*Lw[1], t11, Bw[1]*Rw[2], t12)
    s4[(1 * PXT + pxl) * 17 + ch4] = v1;
    BLEND4(v3, Tw[2]*Lw[1], t21, Tw[2]*Rw[2], t22, Bw[3]*Lw[1], t31, Bw[3]*Rw[2], t32)
    s4[(3 * PXT + pxl) * 17 + ch4] = v3;

    #undef LOADT
    #undef BLEND4

    // rare border identity copies (exact): center value = x at (Y,xp)
    if ((Y == 0) | (Y == HH - 1) | (xp == 0) | (xp == WW - 1)) {
        const float4 cv = __ldg((const float4*)(xTb + (size_t)pix * CC) + ch4);
        const float cvv[4] = {cv.x, cv.y, cv.z, cv.w};
        #pragma unroll
        for (int k = 0; k < 4; ++k) {
            const int c = ch4 * 4 + k;
            const size_t base = ((size_t)(b * 5) * CC + c) * HW + pix;
            if (Y == HH - 1)  __stcs(out + base + (size_t)1 * CC * HW, cvv[k]);
            if (Y == 0)       __stcs(out + base + (size_t)3 * CC * HW, cvv[k]);
            if (xp == WW - 1) __stcs(out + base + (size_t)2 * CC * HW, cvv[k]);
            if (xp == 0)      __stcs(out + base + (size_t)4 * CC * HW, cvv[k]);
        }
    }
    __syncthreads();

    float* ob = out + (size_t)(b * 5) * CC * HW + (size_t)Y * WW + X0;

    // vectorized stores: g0, g1, g3 (aligned destinations)
    {
        const int c   = tid >> 2;                 // channel 0..63
        const int px4 = tid & 3;                  // px quad 0..3
        #pragma unroll
        for (int vi = 0; vi < 3; ++vi) {
            const int sl = (vi == 2) ? 3 : vi;
            const float* sb = st + (sl * PXT + px4 * 4) * 68 + c;
            float4 q;
            q.x = sb[0];
            q.y = sb[68];
            q.z = sb[136];
            q.w = sb[204];
            float* p = ob + (size_t)(sl * 64 + c) * HW + px4 * 4;
            bool ok = true;
            if (sl == 1)      { p -= WW; ok = (Y >= 1); }
            else if (sl == 3) { p += WW; ok = (Y <= HH - 2); }
            if (ok) __stcs((float4*)p, q);
        }
    }

    // scalar stores: g2 (x-1), g4 (x+1) — misaligned by 4B
    #pragma unroll
    for (int it = 0; it < 8; ++it) {
        const int idx = tid + it * 256;           // 0..2047
        const int px  = idx & 15;
        const int q   = idx >> 4;                 // 0..127
        const int sl  = (q < 64) ? 2 : 4;
        const int c   = q & 63;
        const float v = st[(sl * PXT + px) * 68 + c];
        float* p = ob + (size_t)(sl * 64 + c) * HW + px;
        bool ok;
        if (sl == 2) { p -= 1; ok = (X0 + px >= 1); }
        else         { p += 1; ok = (X0 + px <= WW - 2); }
        if (ok) __stcs(p, v);
    }
}

extern "C" void kernel_launch(void* const* d_in, const int* in_sizes, int n_in,
                              void* d_out, int out_size) {
    const float* x    = (const float*)d_in[0];
    const float* flow = (const float*)d_in[1];
    float* out        = (float*)d_out;

    dim3 tgrid(HW / 64, 1, BB);     // 1024 x 1 x 4
    obmc_transpose<<<tgrid, 256>>>(x);

    dim3 ggrid(WW / PXT, HH, BB);   // 16 x 256 x 4
    obmc_gather<<<ggrid, 256>>>(flow, out);
}

// round 15
// speedup vs baseline: 1.4046x; 1.2705x over previous
#include <cuda_runtime.h>
#include <cuda_fp16.h>

// OBMC two-pass, channels-last + 5-group fusion.
// R15 = R14 + fp16 gather operand: transpose emits xH[B,HW,C] in __half
//       (pixel row = 128B = one cache line), taps become LDG.64 -> gather
//       L1 wavefronts halve. All math fp32; only x is quantized (~2^-11).

#define BB 4
#define CC 64
#define HH 256
#define WW 256
#define HW (HH * WW)
#define PXT 16

__device__ __half g_xH[(size_t)BB * HW * CC];   // 33.5 MB scratch

// ---------------- Pass 1: transpose+convert x[B,C,H,W] -> xH[B,HW,C] ----------------
// 64px x 64ch tile as four 32x32 subtiles (scalar STS/LDS, bank-bijective),
// 4 independent LDG.128 per thread before the sync (MLP=4).
__global__ __launch_bounds__(256)
void obmc_transpose(const float* __restrict__ x) {
    __shared__ float t[4][32][33];
    const int b   = blockIdx.z;
    const int pb  = blockIdx.x * 64;   // pixel-tile base within HW
    const int tid = threadIdx.x;

    {   // load: ch = tid>>3 (0..31), px quad = tid&7
        const int ch  = tid >> 3;
        const int px4 = tid & 7;
        float4 v[4];
        #pragma unroll
        for (int k = 0; k < 4; ++k) {
            const int chg = (k >> 1) * 32 + ch;
            const int pxg = pb + (k & 1) * 32;
            v[k] = __ldcs((const float4*)(x + ((size_t)b * CC + chg) * HW + pxg) + px4);
        }
        #pragma unroll
        for (int k = 0; k < 4; ++k) {
            t[k][px4 * 4 + 0][ch] = v[k].x;
            t[k][px4 * 4 + 1][ch] = v[k].y;
            t[k][px4 * 4 + 2][ch] = v[k].z;
            t[k][px4 * 4 + 3][ch] = v[k].w;
        }
    }
    __syncthreads();
    {   // store: px = tid>>3 (0..31), ch quad q = tid&7; 4 halfs = STG.64
        const int px = tid >> 3;
        const int q  = tid & 7;
        #pragma unroll
        for (int k = 0; k < 4; ++k) {
            const float2 a = make_float2(t[k][px][q * 4 + 0], t[k][px][q * 4 + 1]);
            const float2 c = make_float2(t[k][px][q * 4 + 2], t[k][px][q * 4 + 3]);
            __half2 h0 = __float22half2_rn(a);
            __half2 h1 = __float22half2_rn(c);
            uint2 u;
            u.x = *(unsigned*)&h0;
            u.y = *(unsigned*)&h1;
            const int pxg = pb + (k & 1) * 32 + px;
            const int chg = (k >> 1) * 32 + q * 4;
            *(uint2*)(g_xH + ((size_t)b * HW + pxg) * CC + chg) = u;
        }
    }
}

// ---------------- Pass 2: fused gather + vectorized store ----------------
__global__ __launch_bounds__(256, 4)
void obmc_gather(const float* __restrict__ flow, float* __restrict__ out) {
    __shared__ __align__(16) float st[5 * PXT * 68];   // [g][px][68]

    const int tid = threadIdx.x;
    const int l   = tid & 31;
    const int w   = tid >> 5;
    const int pxl = (w << 1) | (l >> 4);      // flow pixel 0..15 in block
    const int ch4 = l & 15;                   // 4-channel slice
    const int X0  = blockIdx.x * PXT;
    const int Y   = blockIdx.y;
    const int b   = blockIdx.z;
    const int xp  = X0 + pxl;
    const int pix = Y * WW + xp;

    const float* fb  = flow + (size_t)b * 2 * HW;
    const __half* xTb = g_xH + (size_t)b * HW * CC;

    const float fx = __ldg(fb + pix);
    const float fy = __ldg(fb + HW + pix);

    const float gx = (float)xp + fx;
    const float gy = (float)Y  + fy;
    const float x0f = floorf(gx), y0f = floorf(gy);
    const float wx = gx - x0f,    wy = gy - y0f;
    const int x0 = (int)x0f, y0 = (int)y0f;

    // factorized masked weight tables; rows r=y0-1+i, cols c=x0-1+j
    int rb_[4], cb_[4];
    float Tw[4], Bw[4], Lw[4], Rw[4];
    #pragma unroll
    for (int i = 0; i < 4; ++i) {
        const int r = y0 - 1 + i;
        const float vr = ((unsigned)r < HH) ? 1.f : 0.f;
        rb_[i] = min(max(r, 0), HH - 1) * WW;
        Tw[i] = (1.f - wy) * vr;
        Bw[i] = wy * vr;
        const int c = x0 - 1 + i;
        const float vc = ((unsigned)c < WW) ? 1.f : 0.f;
        cb_[i] = min(max(c, 0), WW - 1);
        Lw[i] = (1.f - wx) * vc;
        Rw[i] = wx * vc;
    }

    // fp16 tap load (LDG.64: one 128B line per pixel-row) -> float4
    #define LOADT(nm, i, j) \
        float4 nm; { \
            const uint2 u_ = __ldg((const uint2*)(xTb + (size_t)(rb_[i] + cb_[j]) * CC) + ch4); \
            const float2 f0_ = __half22float2(*(const __half2*)&u_.x); \
            const float2 f1_ = __half22float2(*(const __half2*)&u_.y); \
            nm = make_float4(f0_.x, f0_.y, f1_.x, f1_.y); }
    #define BLEND4(dst, cA, tA, cB, tB, cC, tC, cD, tD) \
        float4 dst; \
        dst.x = fmaf(cD, tD.x, fmaf(cC, tC.x, fmaf(cB, tB.x, cA * tA.x))); \
        dst.y = fmaf(cD, tD.y, fmaf(cC, tC.y, fmaf(cB, tB.y, cA * tA.y))); \
        dst.z = fmaf(cD, tD.z, fmaf(cC, tC.z, fmaf(cB, tB.z, cA * tA.z))); \
        dst.w = fmaf(cD, tD.w, fmaf(cC, tC.w, fmaf(cB, tB.w, cA * tA.w)));

    float4* s4 = (float4*)st;                 // 17 float4 per px-row

    // ---- wave A: rows 1,2 (8 taps) -> v0, v2, v4 ----
    LOADT(t10, 1, 0) LOADT(t11, 1, 1) LOADT(t12, 1, 2) LOADT(t13, 1, 3)
    LOADT(t20, 2, 0) LOADT(t21, 2, 1) LOADT(t22, 2, 2) LOADT(t23, 2, 3)

    BLEND4(v0, Tw[1]*Lw[1], t11, Tw[1]*Rw[2], t12, Bw[2]*Lw[1], t21, Bw[2]*Rw[2], t22)
    s4[(0 * PXT + pxl) * 17 + ch4] = v0;
    BLEND4(v2, Tw[1]*Lw[0], t10, Tw[1]*Rw[1], t11, Bw[2]*Lw[0], t20, Bw[2]*Rw[1], t21)
    s4[(2 * PXT + pxl) * 17 + ch4] = v2;
    BLEND4(v4, Tw[1]*Lw[2], t12, Tw[1]*Rw[3], t13, Bw[2]*Lw[2], t22, Bw[2]*Rw[3], t23)
    s4[(4 * PXT + pxl) * 17 + ch4] = v4;

    // ---- wave B: rows 0,3 (4 taps) -> v1, v3 ----
    LOADT(t01, 0, 1) LOADT(t02, 0, 2) LOADT(t31, 3, 1) LOADT(t32, 3, 2)

    BLEND4(v1, Tw[0]*Lw[1], t01, Tw[0]*Rw[2], t02, Bw[1]*Lw[1], t11, Bw[1]*Rw[2], t12)
    s4[(1 * PXT + pxl) * 17 + ch4] = v1;
    BLEND4(v3, Tw[2]*Lw[1], t21, Tw[2]*Rw[2], t22, Bw[3]*Lw[1], t31, Bw[3]*Rw[2], t32)
    s4[(3 * PXT + pxl) * 17 + ch4] = v3;

    #undef BLEND4

    // rare border identity copies (exact w.r.t. quantized x)
    if ((Y == 0) | (Y == HH - 1) | (xp == 0) | (xp == WW - 1)) {
        const uint2 u_ = __ldg((const uint2*)(xTb + (size_t)pix * CC) + ch4);
        const float2 f0_ = __half22float2(*(const __half2*)&u_.x);
        const float2 f1_ = __half22float2(*(const __half2*)&u_.y);
        const float cvv[4] = {f0_.x, f0_.y, f1_.x, f1_.y};
        #pragma unroll
        for (int k = 0; k < 4; ++k) {
            const int c = ch4 * 4 + k;
            const size_t base = ((size_t)(b * 5) * CC + c) * HW + pix;
            if (Y == HH - 1)  __stcs(out + base + (size_t)1 * CC * HW, cvv[k]);
            if (Y == 0)       __stcs(out + base + (size_t)3 * CC * HW, cvv[k]);
            if (xp == WW - 1) __stcs(out + base + (size_t)2 * CC * HW, cvv[k]);
            if (xp == 0)      __stcs(out + base + (size_t)4 * CC * HW, cvv[k]);
        }
    }
    #undef LOADT
    __syncthreads();

    float* ob = out + (size_t)(b * 5) * CC * HW + (size_t)Y * WW + X0;

    // vectorized stores: g0, g1, g3 (aligned destinations)
    {
        const int c   = tid >> 2;                 // channel 0..63
        const int px4 = tid & 3;                  // px quad 0..3
        #pragma unroll
        for (int vi = 0; vi < 3; ++vi) {
            const int sl = (vi == 2) ? 3 : vi;
            const float* sb = st + (sl * PXT + px4 * 4) * 68 + c;
            float4 q;
            q.x = sb[0];
            q.y = sb[68];
            q.z = sb[136];
            q.w = sb[204];
            float* p = ob + (size_t)(sl * 64 + c) * HW + px4 * 4;
            bool ok = true;
            if (sl == 1)      { p -= WW; ok = (Y >= 1); }
            else if (sl == 3) { p += WW; ok = (Y <= HH - 2); }
            if (ok) __stcs((float4*)p, q);
        }
    }

    // scalar stores: g2 (x-1), g4 (x+1) — misaligned by 4B
    #pragma unroll
    for (int it = 0; it < 8; ++it) {
        const int idx = tid + it * 256;           // 0..2047
        const int px  = idx & 15;
        const int q   = idx >> 4;                 // 0..127
        const int sl  = (q < 64) ? 2 : 4;
        const int c   = q & 63;
        const float v = st[(sl * PXT + px) * 68 + c];
        float* p = ob + (size_t)(sl * 64 + c) * HW + px;
        bool ok;
        if (sl == 2) { p -= 1; ok = (X0 + px >= 1); }
        else         { p += 1; ok = (X0 + px <= WW - 2); }
        if (ok) __stcs(p, v);
    }
}

extern "C" void kernel_launch(void* const* d_in, const int* in_sizes, int n_in,
                              void* d_out, int out_size) {
    const float* x    = (const float*)d_in[0];
    const float* flow = (const float*)d_in[1];
    float* out        = (float*)d_out;

    dim3 tgrid(HW / 64, 1, BB);     // 1024 x 1 x 4
    obmc_transpose<<<tgrid, 256>>>(x);

    dim3 ggrid(WW / PXT, HH, BB);   // 16 x 256 x 4
    obmc_gather<<<ggrid, 256>>>(flow, out);
}

// round 16
// speedup vs baseline: 1.4325x; 1.0199x over previous
#include <cuda_runtime.h>
#include <cuda_fp16.h>

// OBMC two-pass, channels-last + 5-group fusion, fp16 gather operand.
// R16 = R15 + occupancy 5 CTAs/SM (launch_bounds 256,5) + strength-reduced
//       scalar g2/g4 store loop (invariant px, pointer increments).

#define BB 4
#define CC 64
#define HH 256
#define WW 256
#define HW (HH * WW)
#define PXT 16

__device__ __half g_xH[(size_t)BB * HW * CC];   // 33.5 MB scratch

// ---------------- Pass 1: transpose+convert x[B,C,H,W] -> xH[B,HW,C] ----------------
__global__ __launch_bounds__(256)
void obmc_transpose(const float* __restrict__ x) {
    __shared__ float t[4][32][33];
    const int b   = blockIdx.z;
    const int pb  = blockIdx.x * 64;
    const int tid = threadIdx.x;

    {   // load: ch = tid>>3 (0..31), px quad = tid&7; MLP=4
        const int ch  = tid >> 3;
        const int px4 = tid & 7;
        float4 v[4];
        #pragma unroll
        for (int k = 0; k < 4; ++k) {
            const int chg = (k >> 1) * 32 + ch;
            const int pxg = pb + (k & 1) * 32;
            v[k] = __ldcs((const float4*)(x + ((size_t)b * CC + chg) * HW + pxg) + px4);
        }
        #pragma unroll
        for (int k = 0; k < 4; ++k) {
            t[k][px4 * 4 + 0][ch] = v[k].x;
            t[k][px4 * 4 + 1][ch] = v[k].y;
            t[k][px4 * 4 + 2][ch] = v[k].z;
            t[k][px4 * 4 + 3][ch] = v[k].w;
        }
    }
    __syncthreads();
    {   // store: px = tid>>3 (0..31), ch quad q = tid&7; STG.64 of 4 halfs
        const int px = tid >> 3;
        const int q  = tid & 7;
        #pragma unroll
        for (int k = 0; k < 4; ++k) {
            const float2 a = make_float2(t[k][px][q * 4 + 0], t[k][px][q * 4 + 1]);
            const float2 c = make_float2(t[k][px][q * 4 + 2], t[k][px][q * 4 + 3]);
            __half2 h0 = __float22half2_rn(a);
            __half2 h1 = __float22half2_rn(c);
            uint2 u;
            u.x = *(unsigned*)&h0;
            u.y = *(unsigned*)&h1;
            const int pxg = pb + (k & 1) * 32 + px;
            const int chg = (k >> 1) * 32 + q * 4;
            *(uint2*)(g_xH + ((size_t)b * HW + pxg) * CC + chg) = u;
        }
    }
}

// ---------------- Pass 2: fused gather + vectorized store ----------------
__global__ __launch_bounds__(256, 5)
void obmc_gather(const float* __restrict__ flow, float* __restrict__ out) {
    __shared__ __align__(16) float st[5 * PXT * 68];   // [g][px][68]

    const int tid = threadIdx.x;
    const int l   = tid & 31;
    const int w   = tid >> 5;
    const int pxl = (w << 1) | (l >> 4);      // flow pixel 0..15 in block
    const int ch4 = l & 15;                   // 4-channel slice
    const int X0  = blockIdx.x * PXT;
    const int Y   = blockIdx.y;
    const int b   = blockIdx.z;
    const int xp  = X0 + pxl;
    const int pix = Y * WW + xp;

    const float* fb   = flow + (size_t)b * 2 * HW;
    const __half* xTb = g_xH + (size_t)b * HW * CC;

    const float fx = __ldg(fb + pix);
    const float fy = __ldg(fb + HW + pix);

    const float gx = (float)xp + fx;
    const float gy = (float)Y  + fy;
    const float x0f = floorf(gx), y0f = floorf(gy);
    const float wx = gx - x0f,    wy = gy - y0f;
    const int x0 = (int)x0f, y0 = (int)y0f;

    int rb_[4], cb_[4];
    float Tw[4], Bw[4], Lw[4], Rw[4];
    #pragma unroll
    for (int i = 0; i < 4; ++i) {
        const int r = y0 - 1 + i;
        const float vr = ((unsigned)r < HH) ? 1.f : 0.f;
        rb_[i] = min(max(r, 0), HH - 1) * WW;
        Tw[i] = (1.f - wy) * vr;
        Bw[i] = wy * vr;
        const int c = x0 - 1 + i;
        const float vc = ((unsigned)c < WW) ? 1.f : 0.f;
        cb_[i] = min(max(c, 0), WW - 1);
        Lw[i] = (1.f - wx) * vc;
        Rw[i] = wx * vc;
    }

    #define LOADT(nm, i, j) \
        float4 nm; { \
            const uint2 u_ = __ldg((const uint2*)(xTb + (size_t)(rb_[i] + cb_[j]) * CC) + ch4); \
            const float2 f0_ = __half22float2(*(const __half2*)&u_.x); \
            const float2 f1_ = __half22float2(*(const __half2*)&u_.y); \
            nm = make_float4(f0_.x, f0_.y, f1_.x, f1_.y); }
    #define BLEND4(dst, cA, tA, cB, tB, cC, tC, cD, tD) \
        float4 dst; \
        dst.x = fmaf(cD, tD.x, fmaf(cC, tC.x, fmaf(cB, tB.x, cA * tA.x))); \
        dst.y = fmaf(cD, tD.y, fmaf(cC, tC.y, fmaf(cB, tB.y, cA * tA.y))); \
        dst.z = fmaf(cD, tD.z, fmaf(cC, tC.z, fmaf(cB, tB.z, cA * tA.z))); \
        dst.w = fmaf(cD, tD.w, fmaf(cC, tC.w, fmaf(cB, tB.w, cA * tA.w)));

    float4* s4 = (float4*)st;                 // 17 float4 per px-row

    // ---- wave A: rows 1,2 (8 taps) -> v0, v2, v4 ----
    LOADT(t10, 1, 0) LOADT(t11, 1, 1) LOADT(t12, 1, 2) LOADT(t13, 1, 3)
    LOADT(t20, 2, 0) LOADT(t21, 2, 1) LOADT(t22, 2, 2) LOADT(t23, 2, 3)

    BLEND4(v0, Tw[1]*Lw[1], t11, Tw[1]*Rw[2], t12, Bw[2]*Lw[1], t21, Bw[2]*Rw[2], t22)
    s4[(0 * PXT + pxl) * 17 + ch4] = v0;
    BLEND4(v2, Tw[1]*Lw[0], t10, Tw[1]*Rw[1], t11, Bw[2]*Lw[0], t20, Bw[2]*Rw[1], t21)
    s4[(2 * PXT + pxl) * 17 + ch4] = v2;
    BLEND4(v4, Tw[1]*Lw[2], t12, Tw[1]*Rw[3], t13, Bw[2]*Lw[2], t22, Bw[2]*Rw[3], t23)
    s4[(4 * PXT + pxl) * 17 + ch4] = v4;

    // ---- wave B: rows 0,3 (4 taps) -> v1, v3 ----
    LOADT(t01, 0, 1) LOADT(t02, 0, 2) LOADT(t31, 3, 1) LOADT(t32, 3, 2)

    BLEND4(v1, Tw[0]*Lw[1], t01, Tw[0]*Rw[2], t02, Bw[1]*Lw[1], t11, Bw[1]*Rw[2], t12)
    s4[(1 * PXT + pxl) * 17 + ch4] = v1;
    BLEND4(v3, Tw[2]*Lw[1], t21, Tw[2]*Rw[2], t22, Bw[3]*Lw[1], t31, Bw[3]*Rw[2], t32)
    s4[(3 * PXT + pxl) * 17 + ch4] = v3;

    #undef BLEND4

    // rare border identity copies (exact w.r.t. quantized x)
    if ((Y == 0) | (Y == HH - 1) | (xp == 0) | (xp == WW - 1)) {
        const uint2 u_ = __ldg((const uint2*)(xTb + (size_t)pix * CC) + ch4);
        const float2 f0_ = __half22float2(*(const __half2*)&u_.x);
        const float2 f1_ = __half22float2(*(const __half2*)&u_.y);
        const float cvv[4] = {f0_.x, f0_.y, f1_.x, f1_.y};
        #pragma unroll
        for (int k = 0; k < 4; ++k) {
            const int c = ch4 * 4 + k;
            const size_t base = ((size_t)(b * 5) * CC + c) * HW + pix;
            if (Y == HH - 1)  __stcs(out + base + (size_t)1 * CC * HW, cvv[k]);
            if (Y == 0)       __stcs(out + base + (size_t)3 * CC * HW, cvv[k]);
            if (xp == WW - 1) __stcs(out + base + (size_t)2 * CC * HW, cvv[k]);
            if (xp == 0)      __stcs(out + base + (size_t)4 * CC * HW, cvv[k]);
        }
    }
    #undef LOADT
    __syncthreads();

    float* ob = out + (size_t)(b * 5) * CC * HW + (size_t)Y * WW + X0;

    // vectorized stores: g0, g1, g3 (aligned destinations)
    {
        const int c   = tid >> 2;                 // channel 0..63
        const int px4 = tid & 3;                  // px quad 0..3
        #pragma unroll
        for (int vi = 0; vi < 3; ++vi) {
            const int sl = (vi == 2) ? 3 : vi;
            const float* sb = st + (sl * PXT + px4 * 4) * 68 + c;
            float4 q;
            q.x = sb[0];
            q.y = sb[68];
            q.z = sb[136];
            q.w = sb[204];
            float* p = ob + (size_t)(sl * 64 + c) * HW + px4 * 4;
            bool ok = true;
            if (sl == 1)      { p -= WW; ok = (Y >= 1); }
            else if (sl == 3) { p += WW; ok = (Y <= HH - 2); }
            if (ok) __stcs((float4*)p, q);
        }
    }

    // scalar stores g2/g4, strength-reduced: px invariant per thread,
    // channel walks +16 via pointer increments; predicates hoisted.
    {
        const int px = tid & 15;                  // invariant
        const int q0 = tid >> 4;                  // 0..15 (starting channel)
        const bool ok2 = (X0 + px >= 1);
        const bool ok4 = (X0 + px <= WW - 2);

        const float* s2 = st + (2 * PXT + px) * 68 + q0;
        const float* s4r = st + (4 * PXT + px) * 68 + q0;
        float* p2 = ob + (size_t)(2 * 64 + q0) * HW + px - 1;
        float* p4 = ob + (size_t)(4 * 64 + q0) * HW + px + 1;

        if (ok2) {
            #pragma unroll
            for (int it = 0; it < 4; ++it)
                __stcs(p2 + (size_t)(16 * it) * HW, s2[16 * it]);
        }
        if (ok4) {
            #pragma unroll
            for (int it = 0; it < 4; ++it)
                __stcs(p4 + (size_t)(16 * it) * HW, s4r[16 * it]);
        }
    }
}

extern "C" void kernel_launch(void* const* d_in, const int* in_sizes, int n_in,
                              void* d_out, int out_size) {
    const float* x    = (const float*)d_in[0];
    const float* flow = (const float*)d_in[1];
    float* out        = (float*)d_out;

    dim3 tgrid(HW / 64, 1, BB);     // 1024 x 1 x 4
    obmc_transpose<<<tgrid, 256>>>(x);

    dim3 ggrid(WW / PXT, HH, BB);   // 16 x 256 x 4
    obmc_gather<<<ggrid, 256>>>(flow, out);
}

// round 17
// speedup vs baseline: 1.4630x; 1.0212x over previous
#include <cuda_runtime.h>
#include <cuda_fp16.h>

// OBMC two-pass, channels-last + 5-group fusion, fp16 operand + half2 math.
// R17 = R16 + packed half2 blending (no per-tap dequant; HFMA2 pipeline),
//       launch_bounds(256,6) for ~70% occupancy.

#define BB 4
#define CC 64
#define HH 256
#define WW 256
#define HW (HH * WW)
#define PXT 16

__device__ __half g_xH[(size_t)BB * HW * CC];   // 33.5 MB scratch

// ---------------- Pass 1: transpose+convert x[B,C,H,W] -> xH[B,HW,C] ----------------
__global__ __launch_bounds__(256)
void obmc_transpose(const float* __restrict__ x) {
    __shared__ float t[4][32][33];
    const int b   = blockIdx.z;
    const int pb  = blockIdx.x * 64;
    const int tid = threadIdx.x;

    {   // load: ch = tid>>3 (0..31), px quad = tid&7; MLP=4
        const int ch  = tid >> 3;
        const int px4 = tid & 7;
        float4 v[4];
        #pragma unroll
        for (int k = 0; k < 4; ++k) {
            const int chg = (k >> 1) * 32 + ch;
            const int pxg = pb + (k & 1) * 32;
            v[k] = __ldcs((const float4*)(x + ((size_t)b * CC + chg) * HW + pxg) + px4);
        }
        #pragma unroll
        for (int k = 0; k < 4; ++k) {
            t[k][px4 * 4 + 0][ch] = v[k].x;
            t[k][px4 * 4 + 1][ch] = v[k].y;
            t[k][px4 * 4 + 2][ch] = v[k].z;
            t[k][px4 * 4 + 3][ch] = v[k].w;
        }
    }
    __syncthreads();
    {   // store: px = tid>>3 (0..31), ch quad q = tid&7; STG.64 of 4 halfs
        const int px = tid >> 3;
        const int q  = tid & 7;
        #pragma unroll
        for (int k = 0; k < 4; ++k) {
            const float2 a = make_float2(t[k][px][q * 4 + 0], t[k][px][q * 4 + 1]);
            const float2 c = make_float2(t[k][px][q * 4 + 2], t[k][px][q * 4 + 3]);
            __half2 h0 = __float22half2_rn(a);
            __half2 h1 = __float22half2_rn(c);
            uint2 u;
            u.x = *(unsigned*)&h0;
            u.y = *(unsigned*)&h1;
            const int pxg = pb + (k & 1) * 32 + px;
            const int chg = (k >> 1) * 32 + q * 4;
            *(uint2*)(g_xH + ((size_t)b * HW + pxg) * CC + chg) = u;
        }
    }
}

// tap = 4 channels as 2 x half2
struct H2x2 { __half2 a, b; };

// ---------------- Pass 2: fused gather (half2 math) + vectorized store ----------------
__global__ __launch_bounds__(256, 6)
void obmc_gather(const float* __restrict__ flow, float* __restrict__ out) {
    __shared__ __align__(16) float st[5 * PXT * 68];   // [g][px][68]

    const int tid = threadIdx.x;
    const int l   = tid & 31;
    const int w   = tid >> 5;
    const int pxl = (w << 1) | (l >> 4);      // flow pixel 0..15 in block
    const int ch4 = l & 15;                   // 4-channel slice
    const int X0  = blockIdx.x * PXT;
    const int Y   = blockIdx.y;
    const int b   = blockIdx.z;
    const int xp  = X0 + pxl;
    const int pix = Y * WW + xp;

    const float* fb   = flow + (size_t)b * 2 * HW;
    const __half* xTb = g_xH + (size_t)b * HW * CC;

    const float fx = __ldg(fb + pix);
    const float fy = __ldg(fb + HW + pix);

    const float gx = (float)xp + fx;
    const float gy = (float)Y  + fy;
    const float x0f = floorf(gx), y0f = floorf(gy);
    const float wx = gx - x0f,    wy = gy - y0f;
    const int x0 = (int)x0f, y0 = (int)y0f;

    int rb_[4], cb_[4];
    __half2 Twh[4], Bwh[4], Lwh[4], Rwh[4];
    #pragma unroll
    for (int i = 0; i < 4; ++i) {
        const int r = y0 - 1 + i;
        const float vr = ((unsigned)r < HH) ? 1.f : 0.f;
        rb_[i] = min(max(r, 0), HH - 1) * WW;
        Twh[i] = __float2half2_rn((1.f - wy) * vr);
        Bwh[i] = __float2half2_rn(wy * vr);
        const int c = x0 - 1 + i;
        const float vc = ((unsigned)c < WW) ? 1.f : 0.f;
        cb_[i] = min(max(c, 0), WW - 1);
        Lwh[i] = __float2half2_rn((1.f - wx) * vc);
        Rwh[i] = __float2half2_rn(wx * vc);
    }

    #define LOADT(nm, i, j) \
        H2x2 nm; { \
            const uint2 u_ = __ldg((const uint2*)(xTb + (size_t)(rb_[i] + cb_[j]) * CC) + ch4); \
            nm.a = *(const __half2*)&u_.x; \
            nm.b = *(const __half2*)&u_.y; }

    // half2 blend of 4 taps; coefficients are half2 broadcasts
    #define BLENDH(dst, c0, t0, c1, t1, c2, t2, c3, t3) \
        H2x2 dst; \
        dst.a = __hmul2(c0, t0.a); \
        dst.b = __hmul2(c0, t0.b); \
        dst.a = __hfma2(c1, t1.a, dst.a); \
        dst.b = __hfma2(c1, t1.b, dst.b); \
        dst.a = __hfma2(c2, t2.a, dst.a); \
        dst.b = __hfma2(c2, t2.b, dst.b); \
        dst.a = __hfma2(c3, t3.a, dst.a); \
        dst.b = __hfma2(c3, t3.b, dst.b);

    #define STAGEH(g, v) { \
        const float2 lo_ = __half22float2(v.a); \
        const float2 hi_ = __half22float2(v.b); \
        *(float4*)&st[((g) * PXT + pxl) * 68 + ch4 * 4] = \
            make_float4(lo_.x, lo_.y, hi_.x, hi_.y); }

    // ---- wave A: rows 1,2 (8 taps) -> v0, v2, v4 ----
    LOADT(t10, 1, 0) LOADT(t11, 1, 1) LOADT(t12, 1, 2) LOADT(t13, 1, 3)
    LOADT(t20, 2, 0) LOADT(t21, 2, 1) LOADT(t22, 2, 2) LOADT(t23, 2, 3)

    {
        BLENDH(v0, __hmul2(Twh[1],Lwh[1]), t11, __hmul2(Twh[1],Rwh[2]), t12,
                   __hmul2(Bwh[2],Lwh[1]), t21, __hmul2(Bwh[2],Rwh[2]), t22)
        STAGEH(0, v0)
    }
    {
        BLENDH(v2, __hmul2(Twh[1],Lwh[0]), t10, __hmul2(Twh[1],Rwh[1]), t11,
                   __hmul2(Bwh[2],Lwh[0]), t20, __hmul2(Bwh[2],Rwh[1]), t21)
        STAGEH(2, v2)
    }
    {
        BLENDH(v4, __hmul2(Twh[1],Lwh[2]), t12, __hmul2(Twh[1],Rwh[3]), t13,
                   __hmul2(Bwh[2],Lwh[2]), t22, __hmul2(Bwh[2],Rwh[3]), t23)
        STAGEH(4, v4)
    }

    // ---- wave B: rows 0,3 (4 taps) -> v1, v3 ----
    LOADT(t01, 0, 1) LOADT(t02, 0, 2) LOADT(t31, 3, 1) LOADT(t32, 3, 2)

    {
        BLENDH(v1, __hmul2(Twh[0],Lwh[1]), t01, __hmul2(Twh[0],Rwh[2]), t02,
                   __hmul2(Bwh[1],Lwh[1]), t11, __hmul2(Bwh[1],Rwh[2]), t12)
        STAGEH(1, v1)
    }
    {
        BLENDH(v3, __hmul2(Twh[2],Lwh[1]), t21, __hmul2(Twh[2],Rwh[2]), t22,
                   __hmul2(Bwh[3],Lwh[1]), t31, __hmul2(Bwh[3],Rwh[2]), t32)
        STAGEH(3, v3)
    }

    #undef BLENDH
    #undef STAGEH

    // rare border identity copies (exact w.r.t. quantized x)
    if ((Y == 0) | (Y == HH - 1) | (xp == 0) | (xp == WW - 1)) {
        H2x2 cv;
        {
            const uint2 u_ = __ldg((const uint2*)(xTb + (size_t)pix * CC) + ch4);
            cv.a = *(const __half2*)&u_.x;
            cv.b = *(const __half2*)&u_.y;
        }
        const float2 lo = __half22float2(cv.a);
        const float2 hi = __half22float2(cv.b);
        const float cvv[4] = {lo.x, lo.y, hi.x, hi.y};
        #pragma unroll
        for (int k = 0; k < 4; ++k) {
            const int c = ch4 * 4 + k;
            const size_t base = ((size_t)(b * 5) * CC + c) * HW + pix;
            if (Y == HH - 1)  __stcs(out + base + (size_t)1 * CC * HW, cvv[k]);
            if (Y == 0)       __stcs(out + base + (size_t)3 * CC * HW, cvv[k]);
            if (xp == WW - 1) __stcs(out + base + (size_t)2 * CC * HW, cvv[k]);
            if (xp == 0)      __stcs(out + base + (size_t)4 * CC * HW, cvv[k]);
        }
    }
    #undef LOADT
    __syncthreads();

    float* ob = out + (size_t)(b * 5) * CC * HW + (size_t)Y * WW + X0;

    // vectorized stores: g0, g1, g3 (aligned destinations)
    {
        const int c   = tid >> 2;                 // channel 0..63
        const int px4 = tid & 3;                  // px quad 0..3
        #pragma unroll
        for (int vi = 0; vi < 3; ++vi) {
            const int sl = (vi == 2) ? 3 : vi;
            const float* sb = st + (sl * PXT + px4 * 4) * 68 + c;
            float4 q;
            q.x = sb[0];
            q.y = sb[68];
            q.z = sb[136];
            q.w = sb[204];
            float* p = ob + (size_t)(sl * 64 + c) * HW + px4 * 4;
            bool ok = true;
            if (sl == 1)      { p -= WW; ok = (Y >= 1); }
            else if (sl == 3) { p += WW; ok = (Y <= HH - 2); }
            if (ok) __stcs((float4*)p, q);
        }
    }

    // scalar stores g2/g4, strength-reduced
    {
        const int px = tid & 15;                  // invariant
        const int q0 = tid >> 4;                  // 0..15 (starting channel)
        const bool ok2 = (X0 + px >= 1);
        const bool ok4 = (X0 + px <= WW - 2);

        const float* s2  = st + (2 * PXT + px) * 68 + q0;
        const float* s4r = st + (4 * PXT + px) * 68 + q0;
        float* p2 = ob + (size_t)(2 * 64 + q0) * HW + px - 1;
        float* p4 = ob + (size_t)(4 * 64 + q0) * HW + px + 1;

        if (ok2) {
            #pragma unroll
            for (int it = 0; it < 4; ++it)
                __stcs(p2 + (size_t)(16 * it) * HW, s2[16 * it]);
        }
        if (ok4) {
            #pragma unroll
            for (int it = 0; it < 4; ++it)
                __stcs(p4 + (size_t)(16 * it) * HW, s4r[16 * it]);
        }
    }
}

extern "C" void kernel_launch(void* const* d_in, const int* in_sizes, int n_in,
                              void* d_out, int out_size) {
    const float* x    = (const float*)d_in[0];
    const float* flow = (const float*)d_in[1];
    float* out        = (float*)d_out;

    dim3 tgrid(HW / 64, 1, BB);     // 1024 x 1 x 4
    obmc_transpose<<<tgrid, 256>>>(x);

    dim3 ggrid(WW / PXT, HH, BB);   // 16 x 256 x 4
    obmc_gather<<<ggrid, 256>>>(flow, out);
}